// round 15
// baseline (speedup 1.0000x reference)
#include <cuda_runtime.h>
#include <cuda_bf16.h>
#include <cstdint>

// velocity = MLP(concat(zone_embedding, person_attrs, time_vec)).
// GCN layers are dead code w.r.t. the output; person/time layer-1
// contributions are row-constant, folded into c1 in-kernel.
//
// R15 = R14 with the fold chains de-exposed: ALL fold inputs (Wd1 upper
// rows, Wt2, pa) staged into smem during phase 1's coalesced LDG burst
// (latency hides under the raw-W wait); bt2/bd1 prefetched to regs at the
// top. Phases 2-3 touch only smem (~250cyc each) instead of R14's exposed
// ~700cyc global chain after barrier 2. Mainloop identical to R14/R12.

#define HID 32
#define H1  64
#define TPB 256            // 8 warps, 32 rows/warp, 256 rows/block

typedef uint32_t u32;

// pack pair (x0 -> low half, x1 -> high half) into bf16x2 hi, residual lo.
__device__ __forceinline__ void split2(float x0, float x1, u32& hi, u32& lo) {
    asm("cvt.rn.bf16x2.f32 %0, %1, %2;" : "=r"(hi) : "f"(x1), "f"(x0));
    float h0 = __uint_as_float(hi << 16);
    float h1 = __uint_as_float(hi & 0xffff0000u);
    float r0 = x0 - h0;
    float r1 = x1 - h1;
    asm("cvt.rn.bf16x2.f32 %0, %1, %2;" : "=r"(lo) : "f"(r1), "f"(r0));
}

__device__ __forceinline__ void mma_bf16(float d[4], const u32 a[4], u32 b0, u32 b1) {
    asm("mma.sync.aligned.m16n8k16.row.col.f32.bf16.bf16.f32 "
        "{%0,%1,%2,%3}, {%4,%5,%6,%7}, {%8,%9}, {%0,%1,%2,%3};"
        : "+f"(d[0]), "+f"(d[1]), "+f"(d[2]), "+f"(d[3])
        : "r"(a[0]), "r"(a[1]), "r"(a[2]), "r"(a[3]), "r"(b0), "r"(b1));
}

// ---------------------------------------------------------------------------
__global__ void __launch_bounds__(TPB, 2)
velo_kernel(const float* __restrict__ emb,
            const float* __restrict__ t,   const float* __restrict__ pa,
            const float* __restrict__ Wt1, const float* __restrict__ bt1,
            const float* __restrict__ Wt2, const float* __restrict__ bt2,
            const float* __restrict__ Wd1, const float* __restrict__ bd1,
            const float* __restrict__ Wd2, const float* __restrict__ bd2,
            const float* __restrict__ Wd3, const float* __restrict__ bd3,
            float* __restrict__ out, int nrows)
{
    __shared__ __align__(16) float s_raw[5120];     // 20KB raw W1|W2|W3
    __shared__ __align__(16) float s_upper[1536];   // 6KB Wd1 rows 32..55
    __shared__ __align__(16) float s_wt2[256];      // 1KB Wt2
    __shared__ __align__(16) uint4 s_frag[1280];    // 20KB packed B-frags
    __shared__ __align__(16) float s_c1[64];
    __shared__ float s_u[16], s_tv[16], s_pa[8];

    const int tid  = threadIdx.x;
    const int warp = tid >> 5;
    const int lane = tid & 31;
    const int g = lane >> 2, tq = lane & 3;
    const int row_base = blockIdx.x * 256 + warp * 32;

    // ---- A1 fragments up front (independent of packing) ----
    const float2 zero2 = make_float2(0.0f, 0.0f);
    int ra[2], rb[2];
    #pragma unroll
    for (int mt = 0; mt < 2; ++mt) { ra[mt] = row_base + 16 * mt + g; rb[mt] = ra[mt] + 8; }

    u32 A1h[2][2][4], A1l[2][2][4];
    if (row_base < nrows) {
        #pragma unroll
        for (int mt = 0; mt < 2; ++mt) {
            #pragma unroll
            for (int kt = 0; kt < 2; ++kt) {
                float2 p0 = (ra[mt] < nrows) ? *reinterpret_cast<const float2*>(emb + (size_t)ra[mt] * 32 + 16 * kt + 2 * tq)     : zero2;
                float2 p1 = (rb[mt] < nrows) ? *reinterpret_cast<const float2*>(emb + (size_t)rb[mt] * 32 + 16 * kt + 2 * tq)     : zero2;
                float2 p2 = (ra[mt] < nrows) ? *reinterpret_cast<const float2*>(emb + (size_t)ra[mt] * 32 + 16 * kt + 8 + 2 * tq) : zero2;
                float2 p3 = (rb[mt] < nrows) ? *reinterpret_cast<const float2*>(emb + (size_t)rb[mt] * 32 + 16 * kt + 8 + 2 * tq) : zero2;
                split2(p0.x, p0.y, A1h[mt][kt][0], A1l[mt][kt][0]);
                split2(p1.x, p1.y, A1h[mt][kt][1], A1l[mt][kt][1]);
                split2(p2.x, p2.y, A1h[mt][kt][2], A1l[mt][kt][2]);
                split2(p3.x, p3.y, A1h[mt][kt][3], A1l[mt][kt][3]);
            }
        }
    }

    // ---- scalar prefetches (latency hidden under phase-1 barrier) ----
    float f_bt2 = 0.0f, f_bd1 = 0.0f;
    if (tid < 16) f_bt2 = bt2[tid];
    if (tid < 64) f_bd1 = bd1[tid];

    // ---- phase 1: stage all weights + fold inputs coalesced; u fold ----
    {
        const float4* wd1v = reinterpret_cast<const float4*>(Wd1);  // rows 0..55; zone=first 512 f4, upper=next 384
        const float4* w2v  = reinterpret_cast<const float4*>(Wd2);
        const float4* w3v  = reinterpret_cast<const float4*>(Wd3);
        float4* rw = reinterpret_cast<float4*>(s_raw);
        float4* up = reinterpret_cast<float4*>(s_upper);
        #pragma unroll
        for (int i = tid; i < 512; i += TPB)  rw[i]        = wd1v[i];
        #pragma unroll
        for (int i = tid; i < 512; i += TPB)  rw[512 + i]  = w2v[i];
        #pragma unroll
        for (int i = tid; i < 256; i += TPB)  rw[1024 + i] = w3v[i];
        #pragma unroll
        for (int i = tid; i < 384; i += TPB)  up[i]        = wd1v[512 + i];
        if (tid < 64) reinterpret_cast<float4*>(s_wt2)[tid] = reinterpret_cast<const float4*>(Wt2)[tid];
        if (tid < 8)  s_pa[tid] = pa[tid];
        if (tid < 16) s_u[tid] = fmaxf(fmaf(t[0], Wt1[tid], bt1[tid]), 0.0f);
    }
    __syncthreads();

    // ---- phase 2: pack frags (LDS scatter -> split2 -> STS); tv fold ----
    if (tid < 16) {
        float a = f_bt2;
        #pragma unroll
        for (int i = 0; i < 16; i++) a = fmaf(s_u[i], s_wt2[i * 16 + tid], a);
        s_tv[tid] = a;
    }
    #pragma unroll
    for (int p = 0; p < 5; ++p) {
        int idx = tid + p * TPB;
        int base, stride, nt, kt, ln;
        if (idx < 512)       { int s = idx;        ln = s & 31; int q = s >> 5; nt = q >> 1; kt = q & 1; base = 0;    stride = 64; }
        else if (idx < 1024) { int s = idx - 512;  ln = s & 31; int q = s >> 5; nt = q >> 2; kt = q & 3; base = 2048; stride = 32; }
        else                 { int s = idx - 1024; ln = s & 31; int q = s >> 5; nt = q >> 1; kt = q & 1; base = 4096; stride = 32; }
        int gg = ln >> 2, tt = ln & 3;
        int col  = 8 * nt + gg;
        int krow = 16 * kt + 2 * tt;
        float w00 = s_raw[base + (krow    ) * stride + col];
        float w01 = s_raw[base + (krow + 1) * stride + col];
        float w10 = s_raw[base + (krow + 8) * stride + col];
        float w11 = s_raw[base + (krow + 9) * stride + col];
        uint4 f;
        split2(w00, w01, f.x, f.z);
        split2(w10, w11, f.y, f.w);
        s_frag[idx] = f;
    }
    __syncthreads();

    // ---- phase 3: c1 fold — smem-only now (~250cyc) ----
    if (tid < H1) {
        float a = f_bd1;
        #pragma unroll
        for (int p = 0; p < 8; p++)  a = fmaf(s_pa[p], s_upper[p * 64 + tid], a);
        #pragma unroll
        for (int i = 0; i < 16; i++) a = fmaf(s_tv[i], s_upper[(8 + i) * 64 + tid], a);
        s_c1[tid] = a;
    }
    __syncthreads();

    if (row_base >= nrows) return;      // after the last barrier

    // ---- layer1 (K=32, N=64): nt-outer, both m-tiles per B fragment ----
    u32 A2h[2][4][4], A2l[2][4][4];
    #pragma unroll
    for (int nt = 0; nt < 8; ++nt) {
        float d[2][4] = {{0.f,0.f,0.f,0.f},{0.f,0.f,0.f,0.f}};
        #pragma unroll
        for (int kt = 0; kt < 2; ++kt) {
            uint4 B = s_frag[(nt * 2 + kt) * 32 + lane];
            #pragma unroll
            for (int mt = 0; mt < 2; ++mt) {
                mma_bf16(d[mt], A1h[mt][kt], B.x, B.y);
                mma_bf16(d[mt], A1h[mt][kt], B.z, B.w);
                mma_bf16(d[mt], A1l[mt][kt], B.x, B.y);
            }
        }
        float2 cb = *reinterpret_cast<const float2*>(s_c1 + 8 * nt + 2 * tq);
        int kt2 = nt >> 1, off = (nt & 1) * 2;
        #pragma unroll
        for (int mt = 0; mt < 2; ++mt) {
            float h0 = fmaxf(d[mt][0] + cb.x, 0.0f);
            float h1 = fmaxf(d[mt][1] + cb.y, 0.0f);
            float h2 = fmaxf(d[mt][2] + cb.x, 0.0f);
            float h3 = fmaxf(d[mt][3] + cb.y, 0.0f);
            split2(h0, h1, A2h[mt][kt2][off],     A2l[mt][kt2][off]);
            split2(h2, h3, A2h[mt][kt2][off + 1], A2l[mt][kt2][off + 1]);
        }
    }

    // ---- layer2 (K=64, N=32) ----
    u32 A3h[2][2][4], A3l[2][2][4];
    #pragma unroll
    for (int nt = 0; nt < 4; ++nt) {
        float d[2][4] = {{0.f,0.f,0.f,0.f},{0.f,0.f,0.f,0.f}};
        #pragma unroll
        for (int kt = 0; kt < 4; ++kt) {
            uint4 B = s_frag[512 + (nt * 4 + kt) * 32 + lane];
            #pragma unroll
            for (int mt = 0; mt < 2; ++mt) {
                mma_bf16(d[mt], A2h[mt][kt], B.x, B.y);
                mma_bf16(d[mt], A2h[mt][kt], B.z, B.w);
                mma_bf16(d[mt], A2l[mt][kt], B.x, B.y);
            }
        }
        float2 bb = *reinterpret_cast<const float2*>(bd2 + 8 * nt + 2 * tq);
        int kt3 = nt >> 1, off = (nt & 1) * 2;
        #pragma unroll
        for (int mt = 0; mt < 2; ++mt) {
            float h0 = fmaxf(d[mt][0] + bb.x, 0.0f);
            float h1 = fmaxf(d[mt][1] + bb.y, 0.0f);
            float h2 = fmaxf(d[mt][2] + bb.x, 0.0f);
            float h3 = fmaxf(d[mt][3] + bb.y, 0.0f);
            split2(h0, h1, A3h[mt][kt3][off],     A3l[mt][kt3][off]);
            split2(h2, h3, A3h[mt][kt3][off + 1], A3l[mt][kt3][off + 1]);
        }
    }

    // ---- layer3 (K=32, N=32) + bias, store ----
    #pragma unroll
    for (int nt = 0; nt < 4; ++nt) {
        float d[2][4] = {{0.f,0.f,0.f,0.f},{0.f,0.f,0.f,0.f}};
        #pragma unroll
        for (int kt = 0; kt < 2; ++kt) {
            uint4 B = s_frag[1024 + (nt * 2 + kt) * 32 + lane];
            #pragma unroll
            for (int mt = 0; mt < 2; ++mt) {
                mma_bf16(d[mt], A3h[mt][kt], B.x, B.y);
                mma_bf16(d[mt], A3h[mt][kt], B.z, B.w);
                mma_bf16(d[mt], A3l[mt][kt], B.x, B.y);
            }
        }
        float2 b3 = *reinterpret_cast<const float2*>(bd3 + 8 * nt + 2 * tq);
        #pragma unroll
        for (int mt = 0; mt < 2; ++mt) {
            if (ra[mt] < nrows)
                *reinterpret_cast<float2*>(out + (size_t)ra[mt] * 32 + 8 * nt + 2 * tq) = make_float2(d[mt][0] + b3.x, d[mt][1] + b3.y);
            if (rb[mt] < nrows)
                *reinterpret_cast<float2*>(out + (size_t)rb[mt] * 32 + 8 * nt + 2 * tq) = make_float2(d[mt][2] + b3.x, d[mt][3] + b3.y);
        }
    }
}

extern "C" void kernel_launch(void* const* d_in, const int* in_sizes, int n_in,
                              void* d_out, int out_size)
{
    const float* t   = (const float*)d_in[0];
    const float* emb = (const float*)d_in[1];
    const float* pa  = (const float*)d_in[3];
    const float* Wt1 = (const float*)d_in[9];
    const float* bt1 = (const float*)d_in[10];
    const float* Wt2 = (const float*)d_in[11];
    const float* bt2 = (const float*)d_in[12];
    const float* Wd1 = (const float*)d_in[13];
    const float* bd1 = (const float*)d_in[14];
    const float* Wd2 = (const float*)d_in[15];
    const float* bd2 = (const float*)d_in[16];
    const float* Wd3 = (const float*)d_in[17];
    const float* bd3 = (const float*)d_in[18];
    float* out = (float*)d_out;

    const int nrows = in_sizes[1] / HID;

    velo_kernel<<<(nrows + 255) / 256, TPB>>>(emb, t, pa, Wt1, bt1, Wt2, bt2,
                                              Wd1, bd1, Wd2, bd2, Wd3, bd3,
                                              out, nrows);
}

// round 16
// speedup vs baseline: 1.3995x; 1.3995x over previous
#include <cuda_runtime.h>
#include <cuda_bf16.h>
#include <cuda_fp16.h>
#include <cstdint>

// velocity = MLP(concat(zone_embedding, person_attrs, time_vec)).
// GCN layers are dead code w.r.t. the output; person/time layer-1
// contributions are row-constant, folded into c1 in-kernel.
//
// R16: single-term fp16 mma.m16n8k16 (fp32 accumulate). The bf16 3-term
// split's 6.6e-6 rel_err had 150x headroom vs the 1e-3 threshold; fp16
// single-term lands ~5e-4 (2x margin) and cuts MMAs 3x, serial HMMA chains
// to 2/4/2, B-frag bytes 2x, and regs to ~90 — attacking the latency bound
// that R13-R15 showed is the plateau. Structure otherwise = R14/R15:
// single kernel, TPB=256, staged two-phase packing, smem-only folds.

#define HID 32
#define H1  64
#define TPB 256            // 8 warps, 32 rows/warp, 256 rows/block

typedef uint32_t u32;

// pack (x0 -> low half, x1 -> high half) into fp16x2.
__device__ __forceinline__ u32 pack_h2(float x0, float x1) {
    u32 h;
    asm("cvt.rn.f16x2.f32 %0, %1, %2;" : "=r"(h) : "f"(x1), "f"(x0));
    return h;
}

__device__ __forceinline__ void mma_f16(float d[4], const u32 a[4], u32 b0, u32 b1) {
    asm("mma.sync.aligned.m16n8k16.row.col.f32.f16.f16.f32 "
        "{%0,%1,%2,%3}, {%4,%5,%6,%7}, {%8,%9}, {%0,%1,%2,%3};"
        : "+f"(d[0]), "+f"(d[1]), "+f"(d[2]), "+f"(d[3])
        : "r"(a[0]), "r"(a[1]), "r"(a[2]), "r"(a[3]), "r"(b0), "r"(b1));
}

// ---------------------------------------------------------------------------
__global__ void __launch_bounds__(TPB)
velo_kernel(const float* __restrict__ emb,
            const float* __restrict__ t,   const float* __restrict__ pa,
            const float* __restrict__ Wt1, const float* __restrict__ bt1,
            const float* __restrict__ Wt2, const float* __restrict__ bt2,
            const float* __restrict__ Wd1, const float* __restrict__ bd1,
            const float* __restrict__ Wd2, const float* __restrict__ bd2,
            const float* __restrict__ Wd3, const float* __restrict__ bd3,
            float* __restrict__ out, int nrows)
{
    __shared__ __align__(16) float s_raw[5120];     // 20KB raw W1|W2|W3
    __shared__ __align__(16) float s_upper[1536];   // 6KB Wd1 rows 32..55
    __shared__ __align__(16) float s_wt2[256];      // 1KB Wt2
    __shared__ __align__(16) uint2 s_frag[1280];    // 10KB packed fp16 B-frags
    __shared__ __align__(16) float s_c1[64];
    __shared__ float s_u[16], s_tv[16], s_pa[8];

    const int tid  = threadIdx.x;
    const int warp = tid >> 5;
    const int lane = tid & 31;
    const int g = lane >> 2, tq = lane & 3;
    const int row_base = blockIdx.x * 256 + warp * 32;

    // ---- A1 fragments up front (independent of packing) ----
    const float2 zero2 = make_float2(0.0f, 0.0f);
    int ra[2], rb[2];
    #pragma unroll
    for (int mt = 0; mt < 2; ++mt) { ra[mt] = row_base + 16 * mt + g; rb[mt] = ra[mt] + 8; }

    u32 A1[2][2][4];
    if (row_base < nrows) {
        #pragma unroll
        for (int mt = 0; mt < 2; ++mt) {
            #pragma unroll
            for (int kt = 0; kt < 2; ++kt) {
                float2 p0 = (ra[mt] < nrows) ? *reinterpret_cast<const float2*>(emb + (size_t)ra[mt] * 32 + 16 * kt + 2 * tq)     : zero2;
                float2 p1 = (rb[mt] < nrows) ? *reinterpret_cast<const float2*>(emb + (size_t)rb[mt] * 32 + 16 * kt + 2 * tq)     : zero2;
                float2 p2 = (ra[mt] < nrows) ? *reinterpret_cast<const float2*>(emb + (size_t)ra[mt] * 32 + 16 * kt + 8 + 2 * tq) : zero2;
                float2 p3 = (rb[mt] < nrows) ? *reinterpret_cast<const float2*>(emb + (size_t)rb[mt] * 32 + 16 * kt + 8 + 2 * tq) : zero2;
                A1[mt][kt][0] = pack_h2(p0.x, p0.y);
                A1[mt][kt][1] = pack_h2(p1.x, p1.y);
                A1[mt][kt][2] = pack_h2(p2.x, p2.y);
                A1[mt][kt][3] = pack_h2(p3.x, p3.y);
            }
        }
    }

    // ---- scalar prefetches ----
    float f_bt2 = 0.0f, f_bd1 = 0.0f;
    if (tid < 16) f_bt2 = bt2[tid];
    if (tid < 64) f_bd1 = bd1[tid];

    // ---- phase 1: stage all weights + fold inputs coalesced; u fold ----
    {
        const float4* wd1v = reinterpret_cast<const float4*>(Wd1);  // rows 0..55
        const float4* w2v  = reinterpret_cast<const float4*>(Wd2);
        const float4* w3v  = reinterpret_cast<const float4*>(Wd3);
        float4* rw = reinterpret_cast<float4*>(s_raw);
        float4* up = reinterpret_cast<float4*>(s_upper);
        #pragma unroll
        for (int i = tid; i < 512; i += TPB)  rw[i]        = wd1v[i];
        #pragma unroll
        for (int i = tid; i < 512; i += TPB)  rw[512 + i]  = w2v[i];
        #pragma unroll
        for (int i = tid; i < 256; i += TPB)  rw[1024 + i] = w3v[i];
        #pragma unroll
        for (int i = tid; i < 384; i += TPB)  up[i]        = wd1v[512 + i];
        if (tid < 64) reinterpret_cast<float4*>(s_wt2)[tid] = reinterpret_cast<const float4*>(Wt2)[tid];
        if (tid < 8)  s_pa[tid] = pa[tid];
        if (tid < 16) s_u[tid] = fmaxf(fmaf(t[0], Wt1[tid], bt1[tid]), 0.0f);
    }
    __syncthreads();

    // ---- phase 2: pack fp16 frags (LDS scatter -> STS); tv fold ----
    if (tid < 16) {
        float a = f_bt2;
        #pragma unroll
        for (int i = 0; i < 16; i++) a = fmaf(s_u[i], s_wt2[i * 16 + tid], a);
        s_tv[tid] = a;
    }
    #pragma unroll
    for (int p = 0; p < 5; ++p) {
        int idx = tid + p * TPB;
        int base, stride, nt, kt, ln;
        if (idx < 512)       { int s = idx;        ln = s & 31; int q = s >> 5; nt = q >> 1; kt = q & 1; base = 0;    stride = 64; }
        else if (idx < 1024) { int s = idx - 512;  ln = s & 31; int q = s >> 5; nt = q >> 2; kt = q & 3; base = 2048; stride = 32; }
        else                 { int s = idx - 1024; ln = s & 31; int q = s >> 5; nt = q >> 1; kt = q & 1; base = 4096; stride = 32; }
        int gg = ln >> 2, tt = ln & 3;
        int col  = 8 * nt + gg;
        int krow = 16 * kt + 2 * tt;
        float w00 = s_raw[base + (krow    ) * stride + col];
        float w01 = s_raw[base + (krow + 1) * stride + col];
        float w10 = s_raw[base + (krow + 8) * stride + col];
        float w11 = s_raw[base + (krow + 9) * stride + col];
        uint2 f;
        f.x = pack_h2(w00, w01);
        f.y = pack_h2(w10, w11);
        s_frag[idx] = f;
    }
    __syncthreads();

    // ---- phase 3: c1 fold (smem-only) ----
    if (tid < H1) {
        float a = f_bd1;
        #pragma unroll
        for (int p = 0; p < 8; p++)  a = fmaf(s_pa[p], s_upper[p * 64 + tid], a);
        #pragma unroll
        for (int i = 0; i < 16; i++) a = fmaf(s_tv[i], s_upper[(8 + i) * 64 + tid], a);
        s_c1[tid] = a;
    }
    __syncthreads();

    if (row_base >= nrows) return;      // after the last barrier

    // ---- layer1 (K=32, N=64): chains of 2 ----
    u32 A2[2][4][4];
    #pragma unroll
    for (int nt = 0; nt < 8; ++nt) {
        float d[2][4] = {{0.f,0.f,0.f,0.f},{0.f,0.f,0.f,0.f}};
        #pragma unroll
        for (int kt = 0; kt < 2; ++kt) {
            uint2 B = s_frag[(nt * 2 + kt) * 32 + lane];
            #pragma unroll
            for (int mt = 0; mt < 2; ++mt)
                mma_f16(d[mt], A1[mt][kt], B.x, B.y);
        }
        float2 cb = *reinterpret_cast<const float2*>(s_c1 + 8 * nt + 2 * tq);
        int kt2 = nt >> 1, off = (nt & 1) * 2;
        #pragma unroll
        for (int mt = 0; mt < 2; ++mt) {
            float h0 = fmaxf(d[mt][0] + cb.x, 0.0f);
            float h1 = fmaxf(d[mt][1] + cb.y, 0.0f);
            float h2 = fmaxf(d[mt][2] + cb.x, 0.0f);
            float h3 = fmaxf(d[mt][3] + cb.y, 0.0f);
            A2[mt][kt2][off]     = pack_h2(h0, h1);
            A2[mt][kt2][off + 1] = pack_h2(h2, h3);
        }
    }

    // ---- layer2 (K=64, N=32): chains of 4 ----
    u32 A3[2][2][4];
    #pragma unroll
    for (int nt = 0; nt < 4; ++nt) {
        float d[2][4] = {{0.f,0.f,0.f,0.f},{0.f,0.f,0.f,0.f}};
        #pragma unroll
        for (int kt = 0; kt < 4; ++kt) {
            uint2 B = s_frag[512 + (nt * 4 + kt) * 32 + lane];
            #pragma unroll
            for (int mt = 0; mt < 2; ++mt)
                mma_f16(d[mt], A2[mt][kt], B.x, B.y);
        }
        float2 bb = *reinterpret_cast<const float2*>(bd2 + 8 * nt + 2 * tq);
        int kt3 = nt >> 1, off = (nt & 1) * 2;
        #pragma unroll
        for (int mt = 0; mt < 2; ++mt) {
            float h0 = fmaxf(d[mt][0] + bb.x, 0.0f);
            float h1 = fmaxf(d[mt][1] + bb.y, 0.0f);
            float h2 = fmaxf(d[mt][2] + bb.x, 0.0f);
            float h3 = fmaxf(d[mt][3] + bb.y, 0.0f);
            A3[mt][kt3][off]     = pack_h2(h0, h1);
            A3[mt][kt3][off + 1] = pack_h2(h2, h3);
        }
    }

    // ---- layer3 (K=32, N=32): chains of 2; + bias, store ----
    #pragma unroll
    for (int nt = 0; nt < 4; ++nt) {
        float d[2][4] = {{0.f,0.f,0.f,0.f},{0.f,0.f,0.f,0.f}};
        #pragma unroll
        for (int kt = 0; kt < 2; ++kt) {
            uint2 B = s_frag[1024 + (nt * 2 + kt) * 32 + lane];
            #pragma unroll
            for (int mt = 0; mt < 2; ++mt)
                mma_f16(d[mt], A3[mt][kt], B.x, B.y);
        }
        float2 b3 = *reinterpret_cast<const float2*>(bd3 + 8 * nt + 2 * tq);
        #pragma unroll
        for (int mt = 0; mt < 2; ++mt) {
            if (ra[mt] < nrows)
                *reinterpret_cast<float2*>(out + (size_t)ra[mt] * 32 + 8 * nt + 2 * tq) = make_float2(d[mt][0] + b3.x, d[mt][1] + b3.y);
            if (rb[mt] < nrows)
                *reinterpret_cast<float2*>(out + (size_t)rb[mt] * 32 + 8 * nt + 2 * tq) = make_float2(d[mt][2] + b3.x, d[mt][3] + b3.y);
        }
    }
}

extern "C" void kernel_launch(void* const* d_in, const int* in_sizes, int n_in,
                              void* d_out, int out_size)
{
    const float* t   = (const float*)d_in[0];
    const float* emb = (const float*)d_in[1];
    const float* pa  = (const float*)d_in[3];
    const float* Wt1 = (const float*)d_in[9];
    const float* bt1 = (const float*)d_in[10];
    const float* Wt2 = (const float*)d_in[11];
    const float* bt2 = (const float*)d_in[12];
    const float* Wd1 = (const float*)d_in[13];
    const float* bd1 = (const float*)d_in[14];
    const float* Wd2 = (const float*)d_in[15];
    const float* bd2 = (const float*)d_in[16];
    const float* Wd3 = (const float*)d_in[17];
    const float* bd3 = (const float*)d_in[18];
    float* out = (float*)d_out;

    const int nrows = in_sizes[1] / HID;

    velo_kernel<<<(nrows + 255) / 256, TPB>>>(emb, t, pa, Wt1, bt1, Wt2, bt2,
                                              Wd1, bd1, Wd2, bd2, Wd3, bd3,
                                              out, nrows);
}

// round 17
// speedup vs baseline: 1.4165x; 1.0121x over previous
#include <cuda_runtime.h>
#include <cuda_bf16.h>
#include <cuda_fp16.h>
#include <cstdint>

// velocity = MLP(concat(zone_embedding, person_attrs, time_vec)).
// GCN layers are dead code w.r.t. the output; person/time layer-1
// contributions are row-constant, folded into c1 in-kernel.
//
// R17 = R16 (single-term fp16 mma.m16n8k16) minus ~250 insts/warp:
//  - biases live in the MMA accumulator init (no epilogue FADDs)
//  - relu done as one max.f16x2 after packing (not 2x fp32 fmax)
//  - B-fragments stored as uint4 (both kt halves adjacent) -> LDS.128,
//    halving fragment-load instructions.

#define HID 32
#define H1  64
#define TPB 256            // 8 warps, 32 rows/warp, 256 rows/block

typedef uint32_t u32;

// pack (x0 -> low half, x1 -> high half) into fp16x2.
__device__ __forceinline__ u32 pack_h2(float x0, float x1) {
    u32 h;
    asm("cvt.rn.f16x2.f32 %0, %1, %2;" : "=r"(h) : "f"(x1), "f"(x0));
    return h;
}
// relu on fp16x2
__device__ __forceinline__ u32 hmax2_zero(u32 p) {
    u32 r, z = 0;
    asm("max.f16x2 %0, %1, %2;" : "=r"(r) : "r"(p), "r"(z));
    return r;
}

__device__ __forceinline__ void mma_f16(float d[4], const u32 a[4], u32 b0, u32 b1) {
    asm("mma.sync.aligned.m16n8k16.row.col.f32.f16.f16.f32 "
        "{%0,%1,%2,%3}, {%4,%5,%6,%7}, {%8,%9}, {%0,%1,%2,%3};"
        : "+f"(d[0]), "+f"(d[1]), "+f"(d[2]), "+f"(d[3])
        : "r"(a[0]), "r"(a[1]), "r"(a[2]), "r"(a[3]), "r"(b0), "r"(b1));
}

// ---------------------------------------------------------------------------
// s_frag4 layout (uint4 per lane, 640 entries = 10KB):
//   [0..255]    W1: [nt=0..7][lane]         .xy = kt0 frag, .zw = kt1 frag
//   [256..511]  W2: [nt*2+j, j=ktpair][lane] .xy = kt(2j), .zw = kt(2j+1)
//   [512..639]  W3: [nt=0..3][lane]         .xy = kt0, .zw = kt1
// ---------------------------------------------------------------------------
__global__ void __launch_bounds__(TPB)
velo_kernel(const float* __restrict__ emb,
            const float* __restrict__ t,   const float* __restrict__ pa,
            const float* __restrict__ Wt1, const float* __restrict__ bt1,
            const float* __restrict__ Wt2, const float* __restrict__ bt2,
            const float* __restrict__ Wd1, const float* __restrict__ bd1,
            const float* __restrict__ Wd2, const float* __restrict__ bd2,
            const float* __restrict__ Wd3, const float* __restrict__ bd3,
            float* __restrict__ out, int nrows)
{
    __shared__ __align__(16) float s_raw[5120];     // 20KB raw W1|W2|W3
    __shared__ __align__(16) float s_upper[1536];   // 6KB Wd1 rows 32..55
    __shared__ __align__(16) float s_wt2[256];      // 1KB Wt2
    __shared__ __align__(16) uint4 s_frag4[640];    // 10KB packed fp16 B-frags
    __shared__ __align__(16) float s_c1[64];
    __shared__ float s_u[16], s_tv[16], s_pa[8];

    const int tid  = threadIdx.x;
    const int warp = tid >> 5;
    const int lane = tid & 31;
    const int g = lane >> 2, tq = lane & 3;
    const int row_base = blockIdx.x * 256 + warp * 32;

    // ---- A1 fragments up front (independent of packing) ----
    const float2 zero2 = make_float2(0.0f, 0.0f);
    int ra[2], rb[2];
    #pragma unroll
    for (int mt = 0; mt < 2; ++mt) { ra[mt] = row_base + 16 * mt + g; rb[mt] = ra[mt] + 8; }

    u32 A1[2][2][4];
    if (row_base < nrows) {
        #pragma unroll
        for (int mt = 0; mt < 2; ++mt) {
            #pragma unroll
            for (int kt = 0; kt < 2; ++kt) {
                float2 p0 = (ra[mt] < nrows) ? *reinterpret_cast<const float2*>(emb + (size_t)ra[mt] * 32 + 16 * kt + 2 * tq)     : zero2;
                float2 p1 = (rb[mt] < nrows) ? *reinterpret_cast<const float2*>(emb + (size_t)rb[mt] * 32 + 16 * kt + 2 * tq)     : zero2;
                float2 p2 = (ra[mt] < nrows) ? *reinterpret_cast<const float2*>(emb + (size_t)ra[mt] * 32 + 16 * kt + 8 + 2 * tq) : zero2;
                float2 p3 = (rb[mt] < nrows) ? *reinterpret_cast<const float2*>(emb + (size_t)rb[mt] * 32 + 16 * kt + 8 + 2 * tq) : zero2;
                A1[mt][kt][0] = pack_h2(p0.x, p0.y);
                A1[mt][kt][1] = pack_h2(p1.x, p1.y);
                A1[mt][kt][2] = pack_h2(p2.x, p2.y);
                A1[mt][kt][3] = pack_h2(p3.x, p3.y);
            }
        }
    }

    // ---- scalar prefetches ----
    float f_bt2 = 0.0f, f_bd1 = 0.0f;
    if (tid < 16) f_bt2 = bt2[tid];
    if (tid < 64) f_bd1 = bd1[tid];

    // ---- phase 1: stage all weights + fold inputs coalesced; u fold ----
    {
        const float4* wd1v = reinterpret_cast<const float4*>(Wd1);  // rows 0..55
        const float4* w2v  = reinterpret_cast<const float4*>(Wd2);
        const float4* w3v  = reinterpret_cast<const float4*>(Wd3);
        float4* rw = reinterpret_cast<float4*>(s_raw);
        float4* up = reinterpret_cast<float4*>(s_upper);
        #pragma unroll
        for (int i = tid; i < 512; i += TPB)  rw[i]        = wd1v[i];
        #pragma unroll
        for (int i = tid; i < 512; i += TPB)  rw[512 + i]  = w2v[i];
        #pragma unroll
        for (int i = tid; i < 256; i += TPB)  rw[1024 + i] = w3v[i];
        #pragma unroll
        for (int i = tid; i < 384; i += TPB)  up[i]        = wd1v[512 + i];
        if (tid < 64) reinterpret_cast<float4*>(s_wt2)[tid] = reinterpret_cast<const float4*>(Wt2)[tid];
        if (tid < 8)  s_pa[tid] = pa[tid];
        if (tid < 16) s_u[tid] = fmaxf(fmaf(t[0], Wt1[tid], bt1[tid]), 0.0f);
    }
    __syncthreads();

    // ---- phase 2: pack fp16 uint4 frags; tv fold ----
    if (tid < 16) {
        float a = f_bt2;
        #pragma unroll
        for (int i = 0; i < 16; i++) a = fmaf(s_u[i], s_wt2[i * 16 + tid], a);
        s_tv[tid] = a;
    }
    #pragma unroll
    for (int p = 0; p < 3; ++p) {
        int idx = tid + p * TPB;
        if (idx < 640) {
            int ln  = idx & 31;
            int grp = idx >> 5;                     // 0..19
            int base, stride, nt, kta, ktb;
            if (grp < 8)       { nt = grp;                                kta = 0;     ktb = 1;      base = 0;    stride = 64; }
            else if (grp < 16) { int s = grp - 8; nt = s >> 1; int j = s & 1; kta = 2*j; ktb = 2*j+1; base = 2048; stride = 32; }
            else               { nt = grp - 16;                           kta = 0;     ktb = 1;      base = 4096; stride = 32; }
            int gg = ln >> 2, tt = ln & 3;
            int col = 8 * nt + gg;
            int ka = 16 * kta + 2 * tt;
            int kb = 16 * ktb + 2 * tt;
            float a00 = s_raw[base + (ka    ) * stride + col];
            float a01 = s_raw[base + (ka + 1) * stride + col];
            float a10 = s_raw[base + (ka + 8) * stride + col];
            float a11 = s_raw[base + (ka + 9) * stride + col];
            float b00 = s_raw[base + (kb    ) * stride + col];
            float b01 = s_raw[base + (kb + 1) * stride + col];
            float b10 = s_raw[base + (kb + 8) * stride + col];
            float b11 = s_raw[base + (kb + 9) * stride + col];
            uint4 f;
            f.x = pack_h2(a00, a01);
            f.y = pack_h2(a10, a11);
            f.z = pack_h2(b00, b01);
            f.w = pack_h2(b10, b11);
            s_frag4[idx] = f;
        }
    }
    __syncthreads();

    // ---- phase 3: c1 fold (smem-only) ----
    if (tid < H1) {
        float a = f_bd1;
        #pragma unroll
        for (int p = 0; p < 8; p++)  a = fmaf(s_pa[p], s_upper[p * 64 + tid], a);
        #pragma unroll
        for (int i = 0; i < 16; i++) a = fmaf(s_tv[i], s_upper[(8 + i) * 64 + tid], a);
        s_c1[tid] = a;
    }
    __syncthreads();

    if (row_base >= nrows) return;      // after the last barrier

    // bias prefetch (overlaps layer1 compute)
    float2 bb_r[4], b3_r[4];
    #pragma unroll
    for (int nt = 0; nt < 4; ++nt) {
        bb_r[nt] = *reinterpret_cast<const float2*>(bd2 + 8 * nt + 2 * tq);
        b3_r[nt] = *reinterpret_cast<const float2*>(bd3 + 8 * nt + 2 * tq);
    }

    // ---- layer1 (K=32, N=64): bias-init accumulators, fp16 relu ----
    u32 A2[2][4][4];
    #pragma unroll
    for (int nt = 0; nt < 8; ++nt) {
        uint4 B = s_frag4[nt * 32 + lane];
        float2 cb = *reinterpret_cast<const float2*>(s_c1 + 8 * nt + 2 * tq);
        float d[2][4] = {{cb.x, cb.y, cb.x, cb.y}, {cb.x, cb.y, cb.x, cb.y}};
        #pragma unroll
        for (int mt = 0; mt < 2; ++mt) {
            mma_f16(d[mt], A1[mt][0], B.x, B.y);
            mma_f16(d[mt], A1[mt][1], B.z, B.w);
        }
        int kt2 = nt >> 1, off = (nt & 1) * 2;
        #pragma unroll
        for (int mt = 0; mt < 2; ++mt) {
            A2[mt][kt2][off]     = hmax2_zero(pack_h2(d[mt][0], d[mt][1]));
            A2[mt][kt2][off + 1] = hmax2_zero(pack_h2(d[mt][2], d[mt][3]));
        }
    }

    // ---- layer2 (K=64, N=32) ----
    u32 A3[2][2][4];
    #pragma unroll
    for (int nt = 0; nt < 4; ++nt) {
        uint4 B0 = s_frag4[256 + (nt * 2 + 0) * 32 + lane];
        uint4 B1 = s_frag4[256 + (nt * 2 + 1) * 32 + lane];
        float2 bb = bb_r[nt];
        float d[2][4] = {{bb.x, bb.y, bb.x, bb.y}, {bb.x, bb.y, bb.x, bb.y}};
        #pragma unroll
        for (int mt = 0; mt < 2; ++mt) {
            mma_f16(d[mt], A2[mt][0], B0.x, B0.y);
            mma_f16(d[mt], A2[mt][1], B0.z, B0.w);
            mma_f16(d[mt], A2[mt][2], B1.x, B1.y);
            mma_f16(d[mt], A2[mt][3], B1.z, B1.w);
        }
        int kt3 = nt >> 1, off = (nt & 1) * 2;
        #pragma unroll
        for (int mt = 0; mt < 2; ++mt) {
            A3[mt][kt3][off]     = hmax2_zero(pack_h2(d[mt][0], d[mt][1]));
            A3[mt][kt3][off + 1] = hmax2_zero(pack_h2(d[mt][2], d[mt][3]));
        }
    }

    // ---- layer3 (K=32, N=32): bias-init; direct stores ----
    #pragma unroll
    for (int nt = 0; nt < 4; ++nt) {
        uint4 B = s_frag4[512 + nt * 32 + lane];
        float2 b3 = b3_r[nt];
        float d[2][4] = {{b3.x, b3.y, b3.x, b3.y}, {b3.x, b3.y, b3.x, b3.y}};
        #pragma unroll
        for (int mt = 0; mt < 2; ++mt) {
            mma_f16(d[mt], A3[mt][0], B.x, B.y);
            mma_f16(d[mt], A3[mt][1], B.z, B.w);
        }
        #pragma unroll
        for (int mt = 0; mt < 2; ++mt) {
            if (ra[mt] < nrows)
                *reinterpret_cast<float2*>(out + (size_t)ra[mt] * 32 + 8 * nt + 2 * tq) = make_float2(d[mt][0], d[mt][1]);
            if (rb[mt] < nrows)
                *reinterpret_cast<float2*>(out + (size_t)rb[mt] * 32 + 8 * nt + 2 * tq) = make_float2(d[mt][2], d[mt][3]);
        }
    }
}

extern "C" void kernel_launch(void* const* d_in, const int* in_sizes, int n_in,
                              void* d_out, int out_size)
{
    const float* t   = (const float*)d_in[0];
    const float* emb = (const float*)d_in[1];
    const float* pa  = (const float*)d_in[3];
    const float* Wt1 = (const float*)d_in[9];
    const float* bt1 = (const float*)d_in[10];
    const float* Wt2 = (const float*)d_in[11];
    const float* bt2 = (const float*)d_in[12];
    const float* Wd1 = (const float*)d_in[13];
    const float* bd1 = (const float*)d_in[14];
    const float* Wd2 = (const float*)d_in[15];
    const float* bd2 = (const float*)d_in[16];
    const float* Wd3 = (const float*)d_in[17];
    const float* bd3 = (const float*)d_in[18];
    float* out = (float*)d_out;

    const int nrows = in_sizes[1] / HID;

    velo_kernel<<<(nrows + 255) / 256, TPB>>>(emb, t, pa, Wt1, bt1, Wt2, bt2,
                                              Wd1, bd1, Wd2, bd2, Wd3, bd3,
                                              out, nrows);
}